// round 1
// baseline (speedup 1.0000x reference)
#include <cuda_runtime.h>

#define C_DIM 512
#define S_DIM 4096
#define NH 8
#define HD 64

// Scratch (allocation-free rule: static __device__ globals)
__device__ float g_Q[2 * C_DIM * S_DIM];   // [n,h,d,s]  (scale folded in)
__device__ float g_K[2 * C_DIM * S_DIM];   // [n,h,d,s]
__device__ float g_V[2 * C_DIM * S_DIM];   // [n,h,s,d]
__device__ float g_A[2 * C_DIM * S_DIM];   // attn out, [n,h,d,s]

// ---------------------------------------------------------------------------
// QKV projection: Y[o,s] = mult * (W[o,:] @ x[n,:,s] + b[o])
// grid (S/64, C/64, 2*3), block 256. z encodes (n, which).
// ---------------------------------------------------------------------------
__global__ __launch_bounds__(256) void proj_kernel(
    const float* __restrict__ x,
    const float* __restrict__ Wq, const float* __restrict__ bq,
    const float* __restrict__ Wk, const float* __restrict__ bk,
    const float* __restrict__ Wv, const float* __restrict__ bv)
{
    __shared__ float As[16][65];   // A transposed: As[k][o], pad avoids STS conflicts
    __shared__ float Bs[16][64];   // Bs[k][s], float4-readable

    const int z = blockIdx.z;
    const int n = z / 3, which = z % 3;
    const float* W; const float* bias; float mult;
    if (which == 0)      { W = Wq; bias = bq; mult = 0.125f; }  // 1/sqrt(64)
    else if (which == 1) { W = Wk; bias = bk; mult = 1.0f; }
    else                 { W = Wv; bias = bv; mult = 1.0f; }

    const int o0 = blockIdx.y * 64;
    const int s0 = blockIdx.x * 64;
    const float* xb = x + (size_t)n * C_DIM * S_DIM;

    const int t  = threadIdx.x;
    const int ty = t >> 4, tx = t & 15;

    float acc[4][4] = {};

    for (int k0 = 0; k0 < C_DIM; k0 += 16) {
        #pragma unroll
        for (int it = 0; it < 4; it++) {
            int e = t + 256 * it;
            int oo = e >> 4, kk = e & 15;
            As[kk][oo] = W[(size_t)(o0 + oo) * C_DIM + k0 + kk];
        }
        #pragma unroll
        for (int it = 0; it < 4; it++) {
            int e = t + 256 * it;
            int kk = e >> 6, ss = e & 63;
            Bs[kk][ss] = xb[(size_t)(k0 + kk) * S_DIM + s0 + ss];
        }
        __syncthreads();
        #pragma unroll
        for (int kk = 0; kk < 16; kk++) {
            float a[4];
            a[0] = As[kk][ty*4+0]; a[1] = As[kk][ty*4+1];
            a[2] = As[kk][ty*4+2]; a[3] = As[kk][ty*4+3];
            float4 b4 = *(const float4*)&Bs[kk][tx*4];
            float b[4] = {b4.x, b4.y, b4.z, b4.w};
            #pragma unroll
            for (int i = 0; i < 4; i++)
                #pragma unroll
                for (int j = 0; j < 4; j++)
                    acc[i][j] += a[i] * b[j];
        }
        __syncthreads();
    }

    if (which == 2) {
        // V -> token-major [n,h,s,d] (scattered scalar stores; one-time 17MB)
        #pragma unroll
        for (int i = 0; i < 4; i++) {
            int o_idx = o0 + ty*4 + i;
            float bi = bias[o_idx];
            int h = o_idx >> 6, dd = o_idx & 63;
            float* vb = g_V + (size_t)(n * NH + h) * S_DIM * HD;
            #pragma unroll
            for (int j = 0; j < 4; j++) {
                int s_idx = s0 + tx*4 + j;
                vb[(size_t)s_idx * HD + dd] = acc[i][j] + bi;
            }
        }
    } else {
        float* out = (which == 0) ? g_Q : g_K;
        #pragma unroll
        for (int i = 0; i < 4; i++) {
            int o_idx = o0 + ty*4 + i;
            float bi = bias[o_idx];
            float4 v;
            v.x = (acc[i][0] + bi) * mult;
            v.y = (acc[i][1] + bi) * mult;
            v.z = (acc[i][2] + bi) * mult;
            v.w = (acc[i][3] + bi) * mult;
            *(float4*)&out[(size_t)(n * C_DIM + o_idx) * S_DIM + s0 + tx*4] = v;
        }
    }
}

// ---------------------------------------------------------------------------
// Flash attention: per (n,h) pair, 64 query rows per block, stream 64-key tiles.
// grid (S/64, 16), block 256. Smem exactly 48KB (Q,K,V tiles).
// ---------------------------------------------------------------------------
__global__ __launch_bounds__(256) void attn_kernel()
{
    __shared__ float Qs[64 * 64];   // Qs[d][r]
    __shared__ float Ks[64 * 64];   // Ks[d][c]
    __shared__ float Vs[64 * 64];   // Vs[c][d]

    const int g  = blockIdx.y;          // n*8 + h
    const int q0 = blockIdx.x * 64;
    const float* Qg = g_Q + (size_t)g * HD * S_DIM;
    const float* Kg = g_K + (size_t)g * HD * S_DIM;
    const float* Vg = g_V + (size_t)g * S_DIM * HD;

    const int t  = threadIdx.x;
    const int ty = t >> 4, tx = t & 15;

    #pragma unroll
    for (int it = 0; it < 16; it++) {
        int e = t + 256 * it;
        int dd = e >> 6, r = e & 63;
        Qs[dd*64 + r] = Qg[(size_t)dd * S_DIM + q0 + r];
    }

    float m_[4], l_[4], o_[4][4];
    #pragma unroll
    for (int i = 0; i < 4; i++) {
        m_[i] = __int_as_float(0xff800000u);  // -inf
        l_[i] = 0.f;
        #pragma unroll
        for (int j = 0; j < 4; j++) o_[i][j] = 0.f;
    }

    for (int kt = 0; kt < 64; kt++) {
        const int k0 = kt * 64;
        __syncthreads();   // prior tile consumers done (also covers Q load on kt=0)
        #pragma unroll
        for (int it = 0; it < 16; it++) {
            int e = t + 256 * it;
            int dd = e >> 6, c = e & 63;
            Ks[dd*64 + c] = Kg[(size_t)dd * S_DIM + k0 + c];
        }
        #pragma unroll
        for (int it = 0; it < 16; it++) {
            int e = t + 256 * it;
            int c = e >> 6, dd = e & 63;
            Vs[c*64 + dd] = Vg[(size_t)(k0 + c) * HD + dd];
        }
        __syncthreads();

        // S tile: s_[i][j] = sum_d Q[d][q] * K[d][k]
        float s_[4][4] = {};
        #pragma unroll 4
        for (int dd = 0; dd < 64; dd++) {
            float4 a4 = *(const float4*)&Qs[dd*64 + ty*4];
            float4 b4 = *(const float4*)&Ks[dd*64 + tx*4];
            float a[4] = {a4.x, a4.y, a4.z, a4.w};
            float b[4] = {b4.x, b4.y, b4.z, b4.w};
            #pragma unroll
            for (int i = 0; i < 4; i++)
                #pragma unroll
                for (int j = 0; j < 4; j++)
                    s_[i][j] += a[i] * b[j];
        }

        // online softmax (row = same-ty lanes; xor 1,2,4,8 stays within tx bits)
        #pragma unroll
        for (int i = 0; i < 4; i++) {
            float mt = fmaxf(fmaxf(s_[i][0], s_[i][1]), fmaxf(s_[i][2], s_[i][3]));
            mt = fmaxf(mt, __shfl_xor_sync(0xffffffffu, mt, 1));
            mt = fmaxf(mt, __shfl_xor_sync(0xffffffffu, mt, 2));
            mt = fmaxf(mt, __shfl_xor_sync(0xffffffffu, mt, 4));
            mt = fmaxf(mt, __shfl_xor_sync(0xffffffffu, mt, 8));
            float mn = fmaxf(m_[i], mt);
            float corr = __expf(m_[i] - mn);
            float ls = 0.f;
            #pragma unroll
            for (int j = 0; j < 4; j++) {
                s_[i][j] = __expf(s_[i][j] - mn);
                ls += s_[i][j];
            }
            ls += __shfl_xor_sync(0xffffffffu, ls, 1);
            ls += __shfl_xor_sync(0xffffffffu, ls, 2);
            ls += __shfl_xor_sync(0xffffffffu, ls, 4);
            ls += __shfl_xor_sync(0xffffffffu, ls, 8);
            l_[i] = l_[i] * corr + ls;
            m_[i] = mn;
            #pragma unroll
            for (int j = 0; j < 4; j++) o_[i][j] *= corr;
        }

        // O += P @ V ; P[q][kk] fetched from owning lane via shfl (no P smem)
        #pragma unroll 1
        for (int kk4 = 0; kk4 < 16; kk4++) {
            int src = (t & 16) + kk4;   // same warp-half (same ty), tx = kk4
            #pragma unroll
            for (int j2 = 0; j2 < 4; j2++) {
                int kk = kk4 * 4 + j2;
                float a0 = __shfl_sync(0xffffffffu, s_[0][j2], src);
                float a1 = __shfl_sync(0xffffffffu, s_[1][j2], src);
                float a2 = __shfl_sync(0xffffffffu, s_[2][j2], src);
                float a3 = __shfl_sync(0xffffffffu, s_[3][j2], src);
                float4 b4 = *(const float4*)&Vs[kk*64 + tx*4];
                o_[0][0] += a0*b4.x; o_[0][1] += a0*b4.y; o_[0][2] += a0*b4.z; o_[0][3] += a0*b4.w;
                o_[1][0] += a1*b4.x; o_[1][1] += a1*b4.y; o_[1][2] += a1*b4.z; o_[1][3] += a1*b4.w;
                o_[2][0] += a2*b4.x; o_[2][1] += a2*b4.y; o_[2][2] += a2*b4.z; o_[2][3] += a2*b4.w;
                o_[3][0] += a3*b4.x; o_[3][1] += a3*b4.y; o_[3][2] += a3*b4.z; o_[3][3] += a3*b4.w;
            }
        }
    }

    // normalize + write [n,h,d,s] for the output-projection GEMM
    #pragma unroll
    for (int i = 0; i < 4; i++) {
        float inv = 1.0f / l_[i];
        int s_idx = q0 + ty*4 + i;
        #pragma unroll
        for (int j = 0; j < 4; j++) {
            int dd = tx*4 + j;
            g_A[(size_t)(g * HD + dd) * S_DIM + s_idx] = o_[i][j] * inv;
        }
    }
}

// ---------------------------------------------------------------------------
// Output projection + residual: out[n,c,s] = gamma*(Wo @ A + bo) + x
// grid (S/64, C/64, 2), block 256.
// ---------------------------------------------------------------------------
__global__ __launch_bounds__(256) void oproj_kernel(
    const float* __restrict__ x, const float* __restrict__ Wo,
    const float* __restrict__ bo, const float* __restrict__ gamma,
    float* __restrict__ out)
{
    __shared__ float As[16][65];
    __shared__ float Bs[16][64];

    const int n  = blockIdx.z;
    const int o0 = blockIdx.y * 64, s0 = blockIdx.x * 64;
    const float* Bg = g_A + (size_t)n * C_DIM * S_DIM;

    const int t  = threadIdx.x;
    const int ty = t >> 4, tx = t & 15;

    float acc[4][4] = {};

    for (int k0 = 0; k0 < C_DIM; k0 += 16) {
        #pragma unroll
        for (int it = 0; it < 4; it++) {
            int e = t + 256 * it;
            int oo = e >> 4, kk = e & 15;
            As[kk][oo] = Wo[(size_t)(o0 + oo) * C_DIM + k0 + kk];
        }
        #pragma unroll
        for (int it = 0; it < 4; it++) {
            int e = t + 256 * it;
            int kk = e >> 6, ss = e & 63;
            Bs[kk][ss] = Bg[(size_t)(k0 + kk) * S_DIM + s0 + ss];
        }
        __syncthreads();
        #pragma unroll
        for (int kk = 0; kk < 16; kk++) {
            float a[4];
            a[0] = As[kk][ty*4+0]; a[1] = As[kk][ty*4+1];
            a[2] = As[kk][ty*4+2]; a[3] = As[kk][ty*4+3];
            float4 b4 = *(const float4*)&Bs[kk][tx*4];
            float b[4] = {b4.x, b4.y, b4.z, b4.w};
            #pragma unroll
            for (int i = 0; i < 4; i++)
                #pragma unroll
                for (int j = 0; j < 4; j++)
                    acc[i][j] += a[i] * b[j];
        }
        __syncthreads();
    }

    const float gam = gamma[0];
    #pragma unroll
    for (int i = 0; i < 4; i++) {
        int c = o0 + ty*4 + i;
        float bi = bo[c];
        size_t base = (size_t)(n * C_DIM + c) * S_DIM + s0 + tx*4;
        float4 xr = *(const float4*)&x[base];
        float4 v;
        v.x = gam * (acc[i][0] + bi) + xr.x;
        v.y = gam * (acc[i][1] + bi) + xr.y;
        v.z = gam * (acc[i][2] + bi) + xr.z;
        v.w = gam * (acc[i][3] + bi) + xr.w;
        *(float4*)&out[base] = v;
    }
}

// ---------------------------------------------------------------------------
extern "C" void kernel_launch(void* const* d_in, const int* in_sizes, int n_in,
                              void* d_out, int out_size)
{
    const float* x     = (const float*)d_in[0];
    const float* Wq    = (const float*)d_in[1];
    const float* bq    = (const float*)d_in[2];
    const float* Wk    = (const float*)d_in[3];
    const float* bk    = (const float*)d_in[4];
    const float* Wv    = (const float*)d_in[5];
    const float* bv    = (const float*)d_in[6];
    const float* Wo    = (const float*)d_in[7];
    const float* bo    = (const float*)d_in[8];
    const float* gamma = (const float*)d_in[9];
    float* out = (float*)d_out;

    dim3 gproj(S_DIM / 64, C_DIM / 64, 2 * 3);
    proj_kernel<<<gproj, 256>>>(x, Wq, bq, Wk, bk, Wv, bv);

    dim3 gattn(S_DIM / 64, 16);
    attn_kernel<<<gattn, 256>>>();

    dim3 gout(S_DIM / 64, C_DIM / 64, 2);
    oproj_kernel<<<gout, 256>>>(x, Wo, bo, gamma, out);
}

// round 3
// speedup vs baseline: 2.9207x; 2.9207x over previous
#include <cuda_runtime.h>
#include <cuda_bf16.h>
#include <cstdint>

#define C_DIM 512
#define S_DIM 4096
#define NH 8
#define HD 64

// Scratch (allocation-free rule: static __device__ globals)
__device__ float g_Q[2 * C_DIM * S_DIM];            // [n,h,d,s], 0.125*log2e folded in
__device__ float g_K[2 * C_DIM * S_DIM];            // [n,h,d,s]
__device__ __nv_bfloat16 g_V[2 * C_DIM * S_DIM];    // [n,h,d,s] bf16
__device__ float g_A[2 * C_DIM * S_DIM];            // attn out, [n,h,d,s]

// ---------------------------------------------------------------------------
// helpers
// ---------------------------------------------------------------------------
__device__ __forceinline__ float ex2f(float x) {
    float y;
    asm("ex2.approx.ftz.f32 %0, %1;" : "=f"(y) : "f"(x));
    return y;
}

__device__ __forceinline__ uint32_t pack_bf16(float lo, float hi) {
    uint32_t r;
    asm("cvt.rn.bf16x2.f32 %0, %1, %2;" : "=r"(r) : "f"(hi), "f"(lo));
    return r;
}

__device__ __forceinline__ void mma_tf32(float* d, const float* a, float b0, float b1) {
    asm volatile(
        "mma.sync.aligned.m16n8k8.row.col.f32.tf32.tf32.f32 "
        "{%0,%1,%2,%3}, {%4,%5,%6,%7}, {%8,%9}, {%0,%1,%2,%3};"
        : "+f"(d[0]), "+f"(d[1]), "+f"(d[2]), "+f"(d[3])
        : "r"(__float_as_uint(a[0])), "r"(__float_as_uint(a[1])),
          "r"(__float_as_uint(a[2])), "r"(__float_as_uint(a[3])),
          "r"(__float_as_uint(b0)), "r"(__float_as_uint(b1)));
}

__device__ __forceinline__ void mma_bf16(float* d, uint32_t a0, uint32_t a1,
                                         uint32_t a2, uint32_t a3,
                                         uint32_t b0, uint32_t b1) {
    asm volatile(
        "mma.sync.aligned.m16n8k16.row.col.f32.bf16.bf16.f32 "
        "{%0,%1,%2,%3}, {%4,%5,%6,%7}, {%8,%9}, {%0,%1,%2,%3};"
        : "+f"(d[0]), "+f"(d[1]), "+f"(d[2]), "+f"(d[3])
        : "r"(a0), "r"(a1), "r"(a2), "r"(a3), "r"(b0), "r"(b1));
}

// ---------------------------------------------------------------------------
// QKV projection: Y[o,s] = W[o,:] @ x[n,:,s] + b[o]  (Q scaled, V -> bf16)
// grid (S/64, C/64, 2*3), block 256.
// ---------------------------------------------------------------------------
__global__ __launch_bounds__(256) void proj_kernel(
    const float* __restrict__ x,
    const float* __restrict__ Wq, const float* __restrict__ bq,
    const float* __restrict__ Wk, const float* __restrict__ bk,
    const float* __restrict__ Wv, const float* __restrict__ bv)
{
    __shared__ float As[16][65];
    __shared__ float Bs[16][64];

    const int z = blockIdx.z;
    const int n = z / 3, which = z % 3;
    const float* W; const float* bias; float mult;
    if (which == 0)      { W = Wq; bias = bq; mult = 0.125f * 1.4426950408889634f; }
    else if (which == 1) { W = Wk; bias = bk; mult = 1.0f; }
    else                 { W = Wv; bias = bv; mult = 1.0f; }

    const int o0 = blockIdx.y * 64;
    const int s0 = blockIdx.x * 64;
    const float* xb = x + (size_t)n * C_DIM * S_DIM;

    const int t  = threadIdx.x;
    const int ty = t >> 4, tx = t & 15;

    float acc[4][4] = {};

    for (int k0 = 0; k0 < C_DIM; k0 += 16) {
        #pragma unroll
        for (int it = 0; it < 4; it++) {
            int e = t + 256 * it;
            int oo = e >> 4, kk = e & 15;
            As[kk][oo] = W[(size_t)(o0 + oo) * C_DIM + k0 + kk];
        }
        #pragma unroll
        for (int it = 0; it < 4; it++) {
            int e = t + 256 * it;
            int kk = e >> 6, ss = e & 63;
            Bs[kk][ss] = xb[(size_t)(k0 + kk) * S_DIM + s0 + ss];
        }
        __syncthreads();
        #pragma unroll
        for (int kk = 0; kk < 16; kk++) {
            float a[4];
            a[0] = As[kk][ty*4+0]; a[1] = As[kk][ty*4+1];
            a[2] = As[kk][ty*4+2]; a[3] = As[kk][ty*4+3];
            float4 b4 = *(const float4*)&Bs[kk][tx*4];
            float b[4] = {b4.x, b4.y, b4.z, b4.w};
            #pragma unroll
            for (int i = 0; i < 4; i++)
                #pragma unroll
                for (int j = 0; j < 4; j++)
                    acc[i][j] += a[i] * b[j];
        }
        __syncthreads();
    }

    if (which == 2) {
        // V -> bf16, d-major [n,h,d,s] (same layout as K, just bf16)
        #pragma unroll
        for (int i = 0; i < 4; i++) {
            int o_idx = o0 + ty*4 + i;
            float bi = bias[o_idx];
            uint2 pk;
            pk.x = pack_bf16(acc[i][0] + bi, acc[i][1] + bi);
            pk.y = pack_bf16(acc[i][2] + bi, acc[i][3] + bi);
            *(uint2*)&g_V[(size_t)(n * C_DIM + o_idx) * S_DIM + s0 + tx*4] = pk;
        }
    } else {
        float* out = (which == 0) ? g_Q : g_K;
        #pragma unroll
        for (int i = 0; i < 4; i++) {
            int o_idx = o0 + ty*4 + i;
            float bi = bias[o_idx];
            float4 v;
            v.x = (acc[i][0] + bi) * mult;
            v.y = (acc[i][1] + bi) * mult;
            v.z = (acc[i][2] + bi) * mult;
            v.w = (acc[i][3] + bi) * mult;
            *(float4*)&out[(size_t)(n * C_DIM + o_idx) * S_DIM + s0 + tx*4] = v;
        }
    }
}

// ---------------------------------------------------------------------------
// Flash attention, tensor cores.
// Block = 128 threads (4 warps); each warp owns 16 query rows; block = 64 rows.
// QK^T: m16n8k8 tf32 (Q frag register-resident). P*V: m16n8k16 bf16 with the
// accumulator->A-fragment layout identity (zero shuffles for P).
// grid (S/64, 16).
// ---------------------------------------------------------------------------
__global__ __launch_bounds__(128) void attn_kernel()
{
    __shared__ float Ks[64][72];            // [dim][key], pad 72 -> conflict-free
    __shared__ __nv_bfloat16 Vs[64][72];    // [dim][key] bf16

    const int g  = blockIdx.y;              // n*8 + h
    const int q0 = blockIdx.x * 64;
    const float* Qg = g_Q + (size_t)g * HD * S_DIM;
    const float* Kg = g_K + (size_t)g * HD * S_DIM;
    const __nv_bfloat16* Vg = g_V + (size_t)g * HD * S_DIM;

    const int t    = threadIdx.x;
    const int w    = t >> 5;
    const int lane = t & 31;
    const int qr   = lane >> 2;             // 0..7 (row-in-group / B n-index)
    const int qc   = lane & 3;              // 0..3 (quad col)
    const int row0 = q0 + w * 16 + qr;      // absolute query row "r"

    // Q fragment: qa[ks][0..3] = Q at rows {r, r+8} x dims {8ks+qc, 8ks+qc+4}
    float qa[8][4];
    #pragma unroll
    for (int ks = 0; ks < 8; ks++) {
        int d0 = ks * 8;
        qa[ks][0] = Qg[(size_t)(d0 + qc)     * S_DIM + row0];
        qa[ks][1] = Qg[(size_t)(d0 + qc)     * S_DIM + row0 + 8];
        qa[ks][2] = Qg[(size_t)(d0 + qc + 4) * S_DIM + row0];
        qa[ks][3] = Qg[(size_t)(d0 + qc + 4) * S_DIM + row0 + 8];
    }

    float o_[8][4];
    #pragma unroll
    for (int ns = 0; ns < 8; ns++)
        #pragma unroll
        for (int j = 0; j < 4; j++) o_[ns][j] = 0.f;
    float m0 = -1e30f, m1 = -1e30f, l0 = 0.f, l1 = 0.f;

    for (int kt = 0; kt < 64; kt++) {
        const int k0 = kt * 64;
        __syncthreads();
        // K tile: 64x64 f32, coalesced float4
        #pragma unroll
        for (int it = 0; it < 8; it++) {
            int e = t + 128 * it;
            int r = e >> 4, c4 = (e & 15) * 4;
            *(float4*)&Ks[r][c4] = *(const float4*)&Kg[(size_t)r * S_DIM + k0 + c4];
        }
        // V tile: 64x64 bf16, coalesced 16B
        #pragma unroll
        for (int it = 0; it < 4; it++) {
            int e = t + 128 * it;
            int r = e >> 3, c8 = (e & 7) * 8;
            *(uint4*)&Vs[r][c8] = *(const uint4*)&Vg[(size_t)r * S_DIM + k0 + c8];
        }
        __syncthreads();

        // ---- S = Q @ K^T (tf32) ----
        float s_[8][4];
        #pragma unroll
        for (int ns = 0; ns < 8; ns++)
            #pragma unroll
            for (int j = 0; j < 4; j++) s_[ns][j] = 0.f;

        #pragma unroll
        for (int ks = 0; ks < 8; ks++) {
            #pragma unroll
            for (int ns = 0; ns < 8; ns++) {
                float b0 = Ks[ks*8 + qc    ][ns*8 + qr];
                float b1 = Ks[ks*8 + qc + 4][ns*8 + qr];
                mma_tf32(s_[ns], qa[ks], b0, b1);
            }
        }

        // ---- online softmax (log2 domain; rows r and r+8) ----
        float mt0 = -1e30f, mt1 = -1e30f;
        #pragma unroll
        for (int ns = 0; ns < 8; ns++) {
            mt0 = fmaxf(mt0, fmaxf(s_[ns][0], s_[ns][1]));
            mt1 = fmaxf(mt1, fmaxf(s_[ns][2], s_[ns][3]));
        }
        mt0 = fmaxf(mt0, __shfl_xor_sync(0xffffffffu, mt0, 1));
        mt0 = fmaxf(mt0, __shfl_xor_sync(0xffffffffu, mt0, 2));
        mt1 = fmaxf(mt1, __shfl_xor_sync(0xffffffffu, mt1, 1));
        mt1 = fmaxf(mt1, __shfl_xor_sync(0xffffffffu, mt1, 2));

        float mn0 = fmaxf(m0, mt0), mn1 = fmaxf(m1, mt1);
        float corr0 = ex2f(m0 - mn0), corr1 = ex2f(m1 - mn1);
        m0 = mn0; m1 = mn1;

        float ls0 = 0.f, ls1 = 0.f;
        #pragma unroll
        for (int ns = 0; ns < 8; ns++) {
            s_[ns][0] = ex2f(s_[ns][0] - mn0);
            s_[ns][1] = ex2f(s_[ns][1] - mn0);
            s_[ns][2] = ex2f(s_[ns][2] - mn1);
            s_[ns][3] = ex2f(s_[ns][3] - mn1);
            ls0 += s_[ns][0] + s_[ns][1];
            ls1 += s_[ns][2] + s_[ns][3];
        }
        ls0 += __shfl_xor_sync(0xffffffffu, ls0, 1);
        ls0 += __shfl_xor_sync(0xffffffffu, ls0, 2);
        ls1 += __shfl_xor_sync(0xffffffffu, ls1, 1);
        ls1 += __shfl_xor_sync(0xffffffffu, ls1, 2);
        l0 = l0 * corr0 + ls0;
        l1 = l1 * corr1 + ls1;

        #pragma unroll
        for (int ns = 0; ns < 8; ns++) {
            o_[ns][0] *= corr0; o_[ns][1] *= corr0;
            o_[ns][2] *= corr1; o_[ns][3] *= corr1;
        }

        // ---- pack P -> bf16 A-fragments (layout identity, no shuffles) ----
        uint32_t pk[8][2];
        #pragma unroll
        for (int ns = 0; ns < 8; ns++) {
            pk[ns][0] = pack_bf16(s_[ns][0], s_[ns][1]);   // row r,   keys 2qc,2qc+1
            pk[ns][1] = pack_bf16(s_[ns][2], s_[ns][3]);   // row r+8
        }

        // ---- O += P @ V (bf16) ----
        #pragma unroll
        for (int ks = 0; ks < 4; ks++) {
            uint32_t a0 = pk[2*ks][0],   a1 = pk[2*ks][1];
            uint32_t a2 = pk[2*ks+1][0], a3 = pk[2*ks+1][1];
            #pragma unroll
            for (int ns = 0; ns < 8; ns++) {
                uint32_t b0 = *(const uint32_t*)&Vs[ns*8 + qr][ks*16 + 2*qc];
                uint32_t b1 = *(const uint32_t*)&Vs[ns*8 + qr][ks*16 + 2*qc + 8];
                mma_bf16(o_[ns], a0, a1, a2, a3, b0, b1);
            }
        }
    }

    // normalize + write [n,h,d,s]
    float inv0 = 1.0f / l0, inv1 = 1.0f / l1;
    #pragma unroll
    for (int ns = 0; ns < 8; ns++) {
        int d = ns * 8 + 2 * qc;
        g_A[(size_t)(g * HD + d)     * S_DIM + row0]     = o_[ns][0] * inv0;
        g_A[(size_t)(g * HD + d + 1) * S_DIM + row0]     = o_[ns][1] * inv0;
        g_A[(size_t)(g * HD + d)     * S_DIM + row0 + 8] = o_[ns][2] * inv1;
        g_A[(size_t)(g * HD + d + 1) * S_DIM + row0 + 8] = o_[ns][3] * inv1;
    }
}

// ---------------------------------------------------------------------------
// Output projection + residual: out[n,c,s] = gamma*(Wo @ A + bo) + x
// grid (S/64, C/64, 2), block 256.
// ---------------------------------------------------------------------------
__global__ __launch_bounds__(256) void oproj_kernel(
    const float* __restrict__ x, const float* __restrict__ Wo,
    const float* __restrict__ bo, const float* __restrict__ gamma,
    float* __restrict__ out)
{
    __shared__ float As[16][65];
    __shared__ float Bs[16][64];

    const int n  = blockIdx.z;
    const int o0 = blockIdx.y * 64, s0 = blockIdx.x * 64;
    const float* Bg = g_A + (size_t)n * C_DIM * S_DIM;

    const int t  = threadIdx.x;
    const int ty = t >> 4, tx = t & 15;

    float acc[4][4] = {};

    for (int k0 = 0; k0 < C_DIM; k0 += 16) {
        #pragma unroll
        for (int it = 0; it < 4; it++) {
            int e = t + 256 * it;
            int oo = e >> 4, kk = e & 15;
            As[kk][oo] = Wo[(size_t)(o0 + oo) * C_DIM + k0 + kk];
        }
        #pragma unroll
        for (int it = 0; it < 4; it++) {
            int e = t + 256 * it;
            int kk = e >> 6, ss = e & 63;
            Bs[kk][ss] = Bg[(size_t)(k0 + kk) * S_DIM + s0 + ss];
        }
        __syncthreads();
        #pragma unroll
        for (int kk = 0; kk < 16; kk++) {
            float a[4];
            a[0] = As[kk][ty*4+0]; a[1] = As[kk][ty*4+1];
            a[2] = As[kk][ty*4+2]; a[3] = As[kk][ty*4+3];
            float4 b4 = *(const float4*)&Bs[kk][tx*4];
            float b[4] = {b4.x, b4.y, b4.z, b4.w};
            #pragma unroll
            for (int i = 0; i < 4; i++)
                #pragma unroll
                for (int j = 0; j < 4; j++)
                    acc[i][j] += a[i] * b[j];
        }
        __syncthreads();
    }

    const float gam = gamma[0];
    #pragma unroll
    for (int i = 0; i < 4; i++) {
        int c = o0 + ty*4 + i;
        float bi = bo[c];
        size_t base = (size_t)(n * C_DIM + c) * S_DIM + s0 + tx*4;
        float4 xr = *(const float4*)&x[base];
        float4 v;
        v.x = gam * (acc[i][0] + bi) + xr.x;
        v.y = gam * (acc[i][1] + bi) + xr.y;
        v.z = gam * (acc[i][2] + bi) + xr.z;
        v.w = gam * (acc[i][3] + bi) + xr.w;
        *(float4*)&out[base] = v;
    }
}

// ---------------------------------------------------------------------------
extern "C" void kernel_launch(void* const* d_in, const int* in_sizes, int n_in,
                              void* d_out, int out_size)
{
    const float* x     = (const float*)d_in[0];
    const float* Wq    = (const float*)d_in[1];
    const float* bq    = (const float*)d_in[2];
    const float* Wk    = (const float*)d_in[3];
    const float* bk    = (const float*)d_in[4];
    const float* Wv    = (const float*)d_in[5];
    const float* bv    = (const float*)d_in[6];
    const float* Wo    = (const float*)d_in[7];
    const float* bo    = (const float*)d_in[8];
    const float* gamma = (const float*)d_in[9];
    float* out = (float*)d_out;

    dim3 gproj(S_DIM / 64, C_DIM / 64, 2 * 3);
    proj_kernel<<<gproj, 256>>>(x, Wq, bq, Wk, bk, Wv, bv);

    dim3 gattn(S_DIM / 64, 16);
    attn_kernel<<<gattn, 128>>>();

    dim3 gout(S_DIM / 64, C_DIM / 64, 2);
    oproj_kernel<<<gout, 256>>>(x, Wo, bo, gamma, out);
}

// round 4
// speedup vs baseline: 4.5551x; 1.5596x over previous
#include <cuda_runtime.h>
#include <cuda_bf16.h>
#include <cstdint>

#define C_DIM 512
#define S_DIM 4096
#define NH 8
#define HD 64

// Scratch (allocation-free rule: static __device__ globals)
__device__ float g_Q[2 * C_DIM * S_DIM];            // [n,h,d,s], 0.125*log2e folded in
__device__ float g_K[2 * C_DIM * S_DIM];            // [n,h,d,s]
__device__ __nv_bfloat16 g_V[2 * C_DIM * S_DIM];    // [n,h,d,s] bf16
__device__ float g_A[2 * C_DIM * S_DIM];            // attn out, [n,h,d,s]

// ---------------------------------------------------------------------------
// helpers
// ---------------------------------------------------------------------------
__device__ __forceinline__ float ex2f(float x) {
    float y;
    asm("ex2.approx.ftz.f32 %0, %1;" : "=f"(y) : "f"(x));
    return y;
}

__device__ __forceinline__ uint32_t pack_bf16(float lo, float hi) {
    uint32_t r;
    asm("cvt.rn.bf16x2.f32 %0, %1, %2;" : "=r"(r) : "f"(hi), "f"(lo));
    return r;
}

__device__ __forceinline__ void mma_tf32(float* d, const float* a, float b0, float b1) {
    asm volatile(
        "mma.sync.aligned.m16n8k8.row.col.f32.tf32.tf32.f32 "
        "{%0,%1,%2,%3}, {%4,%5,%6,%7}, {%8,%9}, {%0,%1,%2,%3};"
        : "+f"(d[0]), "+f"(d[1]), "+f"(d[2]), "+f"(d[3])
        : "r"(__float_as_uint(a[0])), "r"(__float_as_uint(a[1])),
          "r"(__float_as_uint(a[2])), "r"(__float_as_uint(a[3])),
          "r"(__float_as_uint(b0)), "r"(__float_as_uint(b1)));
}

__device__ __forceinline__ void mma_bf16(float* d, uint32_t a0, uint32_t a1,
                                         uint32_t a2, uint32_t a3,
                                         uint32_t b0, uint32_t b1) {
    asm volatile(
        "mma.sync.aligned.m16n8k16.row.col.f32.bf16.bf16.f32 "
        "{%0,%1,%2,%3}, {%4,%5,%6,%7}, {%8,%9}, {%0,%1,%2,%3};"
        : "+f"(d[0]), "+f"(d[1]), "+f"(d[2]), "+f"(d[3])
        : "r"(a0), "r"(a1), "r"(a2), "r"(a3), "r"(b0), "r"(b1));
}

// ---------------------------------------------------------------------------
// Tensor-core GEMM tile body shared by proj/oproj.
// Block 256 thr (8 warps). Tile: M=128 rows (A/output), N=64 cols, K chunk 32.
// A (weights) row-major [M,K]; B [K,N] n-contiguous.
// Each warp: 16 rows (w*16..+16) x 64 cols. acc[ns][4].
// ---------------------------------------------------------------------------
struct GemmSmem {
    float Ws[128][36];   // [o][k] pad 36 -> conflict-free frag loads + stores
    float Bs[32][72];    // [k][s] pad 72 -> conflict-free frag loads
};

__device__ __forceinline__ void gemm_tile_tc(
    GemmSmem& sm, const float* __restrict__ A_gm, const float* __restrict__ B_gm,
    int o0, int s0, float acc[8][4], int t)
{
    const int lane = t & 31;
    const int w    = t >> 5;
    const int qr   = lane >> 2;
    const int qc   = lane & 3;
    const int row0 = w * 16 + qr;

    for (int k0 = 0; k0 < C_DIM; k0 += 32) {
        if (k0) __syncthreads();
        // W tile: 128x32 f32, coalesced float4, conflict-free STS
        #pragma unroll
        for (int it = 0; it < 4; it++) {
            int e = t + 256 * it;
            int o = e >> 3, k4 = (e & 7) * 4;
            *(float4*)&sm.Ws[o][k4] =
                *(const float4*)&A_gm[(size_t)(o0 + o) * C_DIM + k0 + k4];
        }
        // B tile: 32x64 f32
        #pragma unroll
        for (int it = 0; it < 2; it++) {
            int e = t + 256 * it;
            int kk = e >> 4, s4 = (e & 15) * 4;
            *(float4*)&sm.Bs[kk][s4] =
                *(const float4*)&B_gm[(size_t)(k0 + kk) * S_DIM + s0 + s4];
        }
        __syncthreads();

        #pragma unroll
        for (int kk = 0; kk < 32; kk += 8) {
            float a[4];
            a[0] = sm.Ws[row0    ][kk + qc];
            a[1] = sm.Ws[row0 + 8][kk + qc];
            a[2] = sm.Ws[row0    ][kk + qc + 4];
            a[3] = sm.Ws[row0 + 8][kk + qc + 4];
            #pragma unroll
            for (int ns = 0; ns < 8; ns++) {
                float b0 = sm.Bs[kk + qc    ][ns * 8 + qr];
                float b1 = sm.Bs[kk + qc + 4][ns * 8 + qr];
                mma_tf32(acc[ns], a, b0, b1);
            }
        }
    }
}

// ---------------------------------------------------------------------------
// QKV projection (tensor cores): grid (S/64, C/128, 6), block 256.
// ---------------------------------------------------------------------------
__global__ __launch_bounds__(256) void proj_kernel(
    const float* __restrict__ x,
    const float* __restrict__ Wq, const float* __restrict__ bq,
    const float* __restrict__ Wk, const float* __restrict__ bk,
    const float* __restrict__ Wv, const float* __restrict__ bv)
{
    __shared__ GemmSmem sm;

    const int z = blockIdx.z;
    const int n = z / 3, which = z % 3;
    const float* W; const float* bias;
    if (which == 0)      { W = Wq; bias = bq; }
    else if (which == 1) { W = Wk; bias = bk; }
    else                 { W = Wv; bias = bv; }

    const int o0 = blockIdx.y * 128;
    const int s0 = blockIdx.x * 64;
    const float* xb = x + (size_t)n * C_DIM * S_DIM;

    const int t    = threadIdx.x;
    const int lane = t & 31;
    const int w    = t >> 5;
    const int qr   = lane >> 2;
    const int qc   = lane & 3;

    float acc[8][4];
    #pragma unroll
    for (int ns = 0; ns < 8; ns++)
        #pragma unroll
        for (int j = 0; j < 4; j++) acc[ns][j] = 0.f;

    gemm_tile_tc(sm, W, xb, o0, s0, acc, t);

    const int r0 = o0 + w * 16 + qr;
    const int r1 = r0 + 8;
    const float bi0 = bias[r0], bi1 = bias[r1];

    if (which == 2) {
        // V -> bf16, d-major [n,h,d,s]
        #pragma unroll
        for (int ns = 0; ns < 8; ns++) {
            int col = s0 + ns * 8 + 2 * qc;
            *(uint32_t*)&g_V[(size_t)(n * C_DIM + r0) * S_DIM + col] =
                pack_bf16(acc[ns][0] + bi0, acc[ns][1] + bi0);
            *(uint32_t*)&g_V[(size_t)(n * C_DIM + r1) * S_DIM + col] =
                pack_bf16(acc[ns][2] + bi1, acc[ns][3] + bi1);
        }
    } else {
        float* out = (which == 0) ? g_Q : g_K;
        const float mult = (which == 0) ? 0.125f * 1.4426950408889634f : 1.0f;
        #pragma unroll
        for (int ns = 0; ns < 8; ns++) {
            int col = s0 + ns * 8 + 2 * qc;
            float2 v0 = { (acc[ns][0] + bi0) * mult, (acc[ns][1] + bi0) * mult };
            float2 v1 = { (acc[ns][2] + bi1) * mult, (acc[ns][3] + bi1) * mult };
            *(float2*)&out[(size_t)(n * C_DIM + r0) * S_DIM + col] = v0;
            *(float2*)&out[(size_t)(n * C_DIM + r1) * S_DIM + col] = v1;
        }
    }
}

// ---------------------------------------------------------------------------
// Flash attention, tensor cores (unchanged from verified round-3 kernel).
// grid (S/64, 16), block 128.
// ---------------------------------------------------------------------------
__global__ __launch_bounds__(128) void attn_kernel()
{
    __shared__ float Ks[64][72];            // [dim][key]
    __shared__ __nv_bfloat16 Vs[64][72];    // [dim][key] bf16

    const int g  = blockIdx.y;              // n*8 + h
    const int q0 = blockIdx.x * 64;
    const float* Qg = g_Q + (size_t)g * HD * S_DIM;
    const float* Kg = g_K + (size_t)g * HD * S_DIM;
    const __nv_bfloat16* Vg = g_V + (size_t)g * HD * S_DIM;

    const int t    = threadIdx.x;
    const int w    = t >> 5;
    const int lane = t & 31;
    const int qr   = lane >> 2;
    const int qc   = lane & 3;
    const int row0 = q0 + w * 16 + qr;

    float qa[8][4];
    #pragma unroll
    for (int ks = 0; ks < 8; ks++) {
        int d0 = ks * 8;
        qa[ks][0] = Qg[(size_t)(d0 + qc)     * S_DIM + row0];
        qa[ks][1] = Qg[(size_t)(d0 + qc)     * S_DIM + row0 + 8];
        qa[ks][2] = Qg[(size_t)(d0 + qc + 4) * S_DIM + row0];
        qa[ks][3] = Qg[(size_t)(d0 + qc + 4) * S_DIM + row0 + 8];
    }

    float o_[8][4];
    #pragma unroll
    for (int ns = 0; ns < 8; ns++)
        #pragma unroll
        for (int j = 0; j < 4; j++) o_[ns][j] = 0.f;
    float m0 = -1e30f, m1 = -1e30f, l0 = 0.f, l1 = 0.f;

    for (int kt = 0; kt < 64; kt++) {
        const int k0 = kt * 64;
        __syncthreads();
        #pragma unroll
        for (int it = 0; it < 8; it++) {
            int e = t + 128 * it;
            int r = e >> 4, c4 = (e & 15) * 4;
            *(float4*)&Ks[r][c4] = *(const float4*)&Kg[(size_t)r * S_DIM + k0 + c4];
        }
        #pragma unroll
        for (int it = 0; it < 4; it++) {
            int e = t + 128 * it;
            int r = e >> 3, c8 = (e & 7) * 8;
            *(uint4*)&Vs[r][c8] = *(const uint4*)&Vg[(size_t)r * S_DIM + k0 + c8];
        }
        __syncthreads();

        float s_[8][4];
        #pragma unroll
        for (int ns = 0; ns < 8; ns++)
            #pragma unroll
            for (int j = 0; j < 4; j++) s_[ns][j] = 0.f;

        #pragma unroll
        for (int ks = 0; ks < 8; ks++) {
            #pragma unroll
            for (int ns = 0; ns < 8; ns++) {
                float b0 = Ks[ks*8 + qc    ][ns*8 + qr];
                float b1 = Ks[ks*8 + qc + 4][ns*8 + qr];
                mma_tf32(s_[ns], qa[ks], b0, b1);
            }
        }

        float mt0 = -1e30f, mt1 = -1e30f;
        #pragma unroll
        for (int ns = 0; ns < 8; ns++) {
            mt0 = fmaxf(mt0, fmaxf(s_[ns][0], s_[ns][1]));
            mt1 = fmaxf(mt1, fmaxf(s_[ns][2], s_[ns][3]));
        }
        mt0 = fmaxf(mt0, __shfl_xor_sync(0xffffffffu, mt0, 1));
        mt0 = fmaxf(mt0, __shfl_xor_sync(0xffffffffu, mt0, 2));
        mt1 = fmaxf(mt1, __shfl_xor_sync(0xffffffffu, mt1, 1));
        mt1 = fmaxf(mt1, __shfl_xor_sync(0xffffffffu, mt1, 2));

        float mn0 = fmaxf(m0, mt0), mn1 = fmaxf(m1, mt1);
        float corr0 = ex2f(m0 - mn0), corr1 = ex2f(m1 - mn1);
        m0 = mn0; m1 = mn1;

        float ls0 = 0.f, ls1 = 0.f;
        #pragma unroll
        for (int ns = 0; ns < 8; ns++) {
            s_[ns][0] = ex2f(s_[ns][0] - mn0);
            s_[ns][1] = ex2f(s_[ns][1] - mn0);
            s_[ns][2] = ex2f(s_[ns][2] - mn1);
            s_[ns][3] = ex2f(s_[ns][3] - mn1);
            ls0 += s_[ns][0] + s_[ns][1];
            ls1 += s_[ns][2] + s_[ns][3];
        }
        ls0 += __shfl_xor_sync(0xffffffffu, ls0, 1);
        ls0 += __shfl_xor_sync(0xffffffffu, ls0, 2);
        ls1 += __shfl_xor_sync(0xffffffffu, ls1, 1);
        ls1 += __shfl_xor_sync(0xffffffffu, ls1, 2);
        l0 = l0 * corr0 + ls0;
        l1 = l1 * corr1 + ls1;

        #pragma unroll
        for (int ns = 0; ns < 8; ns++) {
            o_[ns][0] *= corr0; o_[ns][1] *= corr0;
            o_[ns][2] *= corr1; o_[ns][3] *= corr1;
        }

        uint32_t pk[8][2];
        #pragma unroll
        for (int ns = 0; ns < 8; ns++) {
            pk[ns][0] = pack_bf16(s_[ns][0], s_[ns][1]);
            pk[ns][1] = pack_bf16(s_[ns][2], s_[ns][3]);
        }

        #pragma unroll
        for (int ks = 0; ks < 4; ks++) {
            uint32_t a0 = pk[2*ks][0],   a1 = pk[2*ks][1];
            uint32_t a2 = pk[2*ks+1][0], a3 = pk[2*ks+1][1];
            #pragma unroll
            for (int ns = 0; ns < 8; ns++) {
                uint32_t b0 = *(const uint32_t*)&Vs[ns*8 + qr][ks*16 + 2*qc];
                uint32_t b1 = *(const uint32_t*)&Vs[ns*8 + qr][ks*16 + 2*qc + 8];
                mma_bf16(o_[ns], a0, a1, a2, a3, b0, b1);
            }
        }
    }

    float inv0 = 1.0f / l0, inv1 = 1.0f / l1;
    #pragma unroll
    for (int ns = 0; ns < 8; ns++) {
        int d = ns * 8 + 2 * qc;
        g_A[(size_t)(g * HD + d)     * S_DIM + row0]     = o_[ns][0] * inv0;
        g_A[(size_t)(g * HD + d + 1) * S_DIM + row0]     = o_[ns][1] * inv0;
        g_A[(size_t)(g * HD + d)     * S_DIM + row0 + 8] = o_[ns][2] * inv1;
        g_A[(size_t)(g * HD + d + 1) * S_DIM + row0 + 8] = o_[ns][3] * inv1;
    }
}

// ---------------------------------------------------------------------------
// Output projection + residual (tensor cores): grid (S/64, C/128, 2), block 256.
// ---------------------------------------------------------------------------
__global__ __launch_bounds__(256) void oproj_kernel(
    const float* __restrict__ x, const float* __restrict__ Wo,
    const float* __restrict__ bo, const float* __restrict__ gamma,
    float* __restrict__ out)
{
    __shared__ GemmSmem sm;

    const int n  = blockIdx.z;
    const int o0 = blockIdx.y * 128, s0 = blockIdx.x * 64;
    const float* Bg = g_A + (size_t)n * C_DIM * S_DIM;

    const int t    = threadIdx.x;
    const int lane = t & 31;
    const int w    = t >> 5;
    const int qr   = lane >> 2;
    const int qc   = lane & 3;

    float acc[8][4];
    #pragma unroll
    for (int ns = 0; ns < 8; ns++)
        #pragma unroll
        for (int j = 0; j < 4; j++) acc[ns][j] = 0.f;

    gemm_tile_tc(sm, Wo, Bg, o0, s0, acc, t);

    const float gam = gamma[0];
    const int r0 = o0 + w * 16 + qr;
    const int r1 = r0 + 8;
    const float bi0 = bo[r0], bi1 = bo[r1];

    #pragma unroll
    for (int ns = 0; ns < 8; ns++) {
        int col = s0 + ns * 8 + 2 * qc;
        size_t i0 = (size_t)(n * C_DIM + r0) * S_DIM + col;
        size_t i1 = (size_t)(n * C_DIM + r1) * S_DIM + col;
        float2 x0 = *(const float2*)&x[i0];
        float2 x1 = *(const float2*)&x[i1];
        float2 v0 = { gam * (acc[ns][0] + bi0) + x0.x,
                      gam * (acc[ns][1] + bi0) + x0.y };
        float2 v1 = { gam * (acc[ns][2] + bi1) + x1.x,
                      gam * (acc[ns][3] + bi1) + x1.y };
        *(float2*)&out[i0] = v0;
        *(float2*)&out[i1] = v1;
    }
}

// ---------------------------------------------------------------------------
extern "C" void kernel_launch(void* const* d_in, const int* in_sizes, int n_in,
                              void* d_out, int out_size)
{
    const float* x     = (const float*)d_in[0];
    const float* Wq    = (const float*)d_in[1];
    const float* bq    = (const float*)d_in[2];
    const float* Wk    = (const float*)d_in[3];
    const float* bk    = (const float*)d_in[4];
    const float* Wv    = (const float*)d_in[5];
    const float* bv    = (const float*)d_in[6];
    const float* Wo    = (const float*)d_in[7];
    const float* bo    = (const float*)d_in[8];
    const float* gamma = (const float*)d_in[9];
    float* out = (float*)d_out;

    dim3 gproj(S_DIM / 64, C_DIM / 128, 2 * 3);
    proj_kernel<<<gproj, 256>>>(x, Wq, bq, Wk, bk, Wv, bv);

    dim3 gattn(S_DIM / 64, 16);
    attn_kernel<<<gattn, 128>>>();

    dim3 gout(S_DIM / 64, C_DIM / 128, 2);
    oproj_kernel<<<gout, 256>>>(x, Wo, bo, gamma, out);
}

// round 5
// speedup vs baseline: 5.8478x; 1.2838x over previous
#include <cuda_runtime.h>
#include <cuda_bf16.h>
#include <cstdint>

#define C_DIM 512
#define S_DIM 4096
#define NH 8
#define HD 64

// Scratch (allocation-free rule: static __device__ globals)
__device__ __nv_bfloat16 g_Qb[2 * NH * S_DIM * HD];  // [n,h,s,d] bf16, 0.125*log2e folded
__device__ __nv_bfloat16 g_Kb[2 * NH * S_DIM * HD];  // [n,h,s,d] bf16
__device__ __nv_bfloat16 g_V [2 * C_DIM * S_DIM];    // [n,h,d,s] bf16
__device__ float         g_A [2 * C_DIM * S_DIM];    // attn out, [n,h,d,s] f32

// ---------------------------------------------------------------------------
// helpers
// ---------------------------------------------------------------------------
__device__ __forceinline__ float ex2f(float x) {
    float y;
    asm("ex2.approx.ftz.f32 %0, %1;" : "=f"(y) : "f"(x));
    return y;
}

__device__ __forceinline__ uint32_t pack_bf16(float lo, float hi) {
    uint32_t r;
    asm("cvt.rn.bf16x2.f32 %0, %1, %2;" : "=r"(r) : "f"(hi), "f"(lo));
    return r;
}

__device__ __forceinline__ void mma_tf32(float* d, const float* a, float b0, float b1) {
    asm volatile(
        "mma.sync.aligned.m16n8k8.row.col.f32.tf32.tf32.f32 "
        "{%0,%1,%2,%3}, {%4,%5,%6,%7}, {%8,%9}, {%0,%1,%2,%3};"
        : "+f"(d[0]), "+f"(d[1]), "+f"(d[2]), "+f"(d[3])
        : "r"(__float_as_uint(a[0])), "r"(__float_as_uint(a[1])),
          "r"(__float_as_uint(a[2])), "r"(__float_as_uint(a[3])),
          "r"(__float_as_uint(b0)), "r"(__float_as_uint(b1)));
}

__device__ __forceinline__ void mma_bf16(float* d, uint32_t a0, uint32_t a1,
                                         uint32_t a2, uint32_t a3,
                                         uint32_t b0, uint32_t b1) {
    asm volatile(
        "mma.sync.aligned.m16n8k16.row.col.f32.bf16.bf16.f32 "
        "{%0,%1,%2,%3}, {%4,%5,%6,%7}, {%8,%9}, {%0,%1,%2,%3};"
        : "+f"(d[0]), "+f"(d[1]), "+f"(d[2]), "+f"(d[3])
        : "r"(a0), "r"(a1), "r"(a2), "r"(a3), "r"(b0), "r"(b1));
}

__device__ __forceinline__ void cp16(void* smem, const void* gmem) {
    uint32_t s = (uint32_t)__cvta_generic_to_shared(smem);
    asm volatile("cp.async.cg.shared.global [%0], [%1], 16;" :: "r"(s), "l"(gmem));
}
#define CP_COMMIT() asm volatile("cp.async.commit_group;")
#define CP_WAIT1()  asm volatile("cp.async.wait_group 1;")

__device__ __forceinline__ size_t qk_idx(int n, int r, int s) {
    return ((size_t)(n * NH + (r >> 6)) * S_DIM + s) * HD + (r & 63);
}

// ---------------------------------------------------------------------------
// Tensor-core GEMM tile body shared by proj/oproj (tf32, verified round 4).
// Block 256 thr (8 warps). Tile: M=128 rows, N=64 cols, K chunk 32.
// ---------------------------------------------------------------------------
struct GemmSmem {
    float Ws[128][36];
    float Bs[32][72];
};

__device__ __forceinline__ void gemm_tile_tc(
    GemmSmem& sm, const float* __restrict__ A_gm, const float* __restrict__ B_gm,
    int o0, int s0, float acc[8][4], int t)
{
    const int lane = t & 31;
    const int w    = t >> 5;
    const int qr   = lane >> 2;
    const int qc   = lane & 3;
    const int row0 = w * 16 + qr;

    for (int k0 = 0; k0 < C_DIM; k0 += 32) {
        if (k0) __syncthreads();
        #pragma unroll
        for (int it = 0; it < 4; it++) {
            int e = t + 256 * it;
            int o = e >> 3, k4 = (e & 7) * 4;
            *(float4*)&sm.Ws[o][k4] =
                *(const float4*)&A_gm[(size_t)(o0 + o) * C_DIM + k0 + k4];
        }
        #pragma unroll
        for (int it = 0; it < 2; it++) {
            int e = t + 256 * it;
            int kk = e >> 4, s4 = (e & 15) * 4;
            *(float4*)&sm.Bs[kk][s4] =
                *(const float4*)&B_gm[(size_t)(k0 + kk) * S_DIM + s0 + s4];
        }
        __syncthreads();

        #pragma unroll
        for (int kk = 0; kk < 32; kk += 8) {
            float a[4];
            a[0] = sm.Ws[row0    ][kk + qc];
            a[1] = sm.Ws[row0 + 8][kk + qc];
            a[2] = sm.Ws[row0    ][kk + qc + 4];
            a[3] = sm.Ws[row0 + 8][kk + qc + 4];
            #pragma unroll
            for (int ns = 0; ns < 8; ns++) {
                float b0 = sm.Bs[kk + qc    ][ns * 8 + qr];
                float b1 = sm.Bs[kk + qc + 4][ns * 8 + qr];
                mma_tf32(acc[ns], a, b0, b1);
            }
        }
    }
}

// ---------------------------------------------------------------------------
// QKV projection: grid (S/64, C/128, 6), block 256.
// Q,K -> bf16 token-major [n,h,s,d]; V -> bf16 d-major [n,h,d,s].
// ---------------------------------------------------------------------------
__global__ __launch_bounds__(256) void proj_kernel(
    const float* __restrict__ x,
    const float* __restrict__ Wq, const float* __restrict__ bq,
    const float* __restrict__ Wk, const float* __restrict__ bk,
    const float* __restrict__ Wv, const float* __restrict__ bv)
{
    __shared__ GemmSmem sm;

    const int z = blockIdx.z;
    const int n = z / 3, which = z % 3;
    const float* W; const float* bias;
    if (which == 0)      { W = Wq; bias = bq; }
    else if (which == 1) { W = Wk; bias = bk; }
    else                 { W = Wv; bias = bv; }

    const int o0 = blockIdx.y * 128;
    const int s0 = blockIdx.x * 64;
    const float* xb = x + (size_t)n * C_DIM * S_DIM;

    const int t    = threadIdx.x;
    const int lane = t & 31;
    const int w    = t >> 5;
    const int qr   = lane >> 2;
    const int qc   = lane & 3;

    float acc[8][4];
    #pragma unroll
    for (int ns = 0; ns < 8; ns++)
        #pragma unroll
        for (int j = 0; j < 4; j++) acc[ns][j] = 0.f;

    gemm_tile_tc(sm, W, xb, o0, s0, acc, t);

    const int r0 = o0 + w * 16 + qr;
    const int r1 = r0 + 8;
    const float bi0 = bias[r0], bi1 = bias[r1];

    if (which == 2) {
        // V -> bf16, d-major [n,h,d,s]
        #pragma unroll
        for (int ns = 0; ns < 8; ns++) {
            int col = s0 + ns * 8 + 2 * qc;
            *(uint32_t*)&g_V[(size_t)(n * C_DIM + r0) * S_DIM + col] =
                pack_bf16(acc[ns][0] + bi0, acc[ns][1] + bi0);
            *(uint32_t*)&g_V[(size_t)(n * C_DIM + r1) * S_DIM + col] =
                pack_bf16(acc[ns][2] + bi1, acc[ns][3] + bi1);
        }
    } else {
        __nv_bfloat16* outb = (which == 0) ? g_Qb : g_Kb;
        const float mult = (which == 0) ? 0.125f * 1.4426950408889634f : 1.0f;
        #pragma unroll
        for (int ns = 0; ns < 8; ns++) {
            int col = s0 + ns * 8 + 2 * qc;
            outb[qk_idx(n, r0, col    )] = __float2bfloat16((acc[ns][0] + bi0) * mult);
            outb[qk_idx(n, r0, col + 1)] = __float2bfloat16((acc[ns][1] + bi0) * mult);
            outb[qk_idx(n, r1, col    )] = __float2bfloat16((acc[ns][2] + bi1) * mult);
            outb[qk_idx(n, r1, col + 1)] = __float2bfloat16((acc[ns][3] + bi1) * mult);
        }
    }
}

// ---------------------------------------------------------------------------
// Flash attention: all-bf16 MMA, cp.async double-buffered K/V.
// Block 256 thr (8 warps), 128 query rows; grid (S/128, 16).
// ---------------------------------------------------------------------------
__global__ __launch_bounds__(256) void attn_kernel()
{
    __shared__ __nv_bfloat16 Ks[2][64][72];   // [stage][key][d]   d-contig
    __shared__ __nv_bfloat16 Vs[2][64][72];   // [stage][d][key]   key-contig

    const int g  = blockIdx.y;                // n*8 + h
    const int q0 = blockIdx.x * 128;
    const __nv_bfloat16* Qg = g_Qb + (size_t)g * S_DIM * HD;
    const __nv_bfloat16* Kg = g_Kb + (size_t)g * S_DIM * HD;
    const __nv_bfloat16* Vg = g_V  + (size_t)g * HD * S_DIM;

    const int t    = threadIdx.x;
    const int w    = t >> 5;
    const int lane = t & 31;
    const int qr   = lane >> 2;
    const int qc   = lane & 3;
    const int row0 = q0 + w * 16 + qr;

    // issue K+V tile kt into stage st (4 cp.async of 16B per thread)
    auto issue = [&](int kt, int st) {
        const int k0 = kt * 64;
        #pragma unroll
        for (int it = 0; it < 2; it++) {
            int e = t + 256 * it;
            int r = e >> 3, c8 = (e & 7) * 8;
            cp16(&Ks[st][r][c8], Kg + (size_t)(k0 + r) * HD + c8);
        }
        #pragma unroll
        for (int it = 0; it < 2; it++) {
            int e = t + 256 * it;
            int r = e >> 3, c8 = (e & 7) * 8;
            cp16(&Vs[st][r][c8], Vg + (size_t)r * S_DIM + k0 + c8);
        }
    };

    issue(0, 0); CP_COMMIT();
    issue(1, 1); CP_COMMIT();

    // Q fragments (bf16, m16n8k16 A layout), register-resident for the block
    uint32_t qa[4][4];
    #pragma unroll
    for (int ks = 0; ks < 4; ks++) {
        int c = ks * 16 + 2 * qc;
        qa[ks][0] = *(const uint32_t*)&Qg[(size_t)row0       * HD + c];
        qa[ks][1] = *(const uint32_t*)&Qg[(size_t)(row0 + 8) * HD + c];
        qa[ks][2] = *(const uint32_t*)&Qg[(size_t)row0       * HD + c + 8];
        qa[ks][3] = *(const uint32_t*)&Qg[(size_t)(row0 + 8) * HD + c + 8];
    }

    float o_[8][4];
    #pragma unroll
    for (int ns = 0; ns < 8; ns++)
        #pragma unroll
        for (int j = 0; j < 4; j++) o_[ns][j] = 0.f;
    float m0 = -1e30f, m1 = -1e30f, l0 = 0.f, l1 = 0.f;

    for (int kt = 0; kt < 64; kt++) {
        const int st = kt & 1;
        CP_WAIT1();
        __syncthreads();

        // ---- S = Q @ K^T (bf16) ----
        float s_[8][4];
        #pragma unroll
        for (int ns = 0; ns < 8; ns++)
            #pragma unroll
            for (int j = 0; j < 4; j++) s_[ns][j] = 0.f;

        #pragma unroll
        for (int ks = 0; ks < 4; ks++) {
            #pragma unroll
            for (int ns = 0; ns < 8; ns++) {
                uint32_t b0 = *(const uint32_t*)&Ks[st][ns*8 + qr][ks*16 + 2*qc];
                uint32_t b1 = *(const uint32_t*)&Ks[st][ns*8 + qr][ks*16 + 2*qc + 8];
                mma_bf16(s_[ns], qa[ks][0], qa[ks][1], qa[ks][2], qa[ks][3], b0, b1);
            }
        }

        // ---- online softmax (log2 domain; rows r and r+8) ----
        float mt0 = -1e30f, mt1 = -1e30f;
        #pragma unroll
        for (int ns = 0; ns < 8; ns++) {
            mt0 = fmaxf(mt0, fmaxf(s_[ns][0], s_[ns][1]));
            mt1 = fmaxf(mt1, fmaxf(s_[ns][2], s_[ns][3]));
        }
        mt0 = fmaxf(mt0, __shfl_xor_sync(0xffffffffu, mt0, 1));
        mt0 = fmaxf(mt0, __shfl_xor_sync(0xffffffffu, mt0, 2));
        mt1 = fmaxf(mt1, __shfl_xor_sync(0xffffffffu, mt1, 1));
        mt1 = fmaxf(mt1, __shfl_xor_sync(0xffffffffu, mt1, 2));

        float mn0 = fmaxf(m0, mt0), mn1 = fmaxf(m1, mt1);
        float corr0 = ex2f(m0 - mn0), corr1 = ex2f(m1 - mn1);
        m0 = mn0; m1 = mn1;

        float ls0 = 0.f, ls1 = 0.f;
        #pragma unroll
        for (int ns = 0; ns < 8; ns++) {
            s_[ns][0] = ex2f(s_[ns][0] - mn0);
            s_[ns][1] = ex2f(s_[ns][1] - mn0);
            s_[ns][2] = ex2f(s_[ns][2] - mn1);
            s_[ns][3] = ex2f(s_[ns][3] - mn1);
            ls0 += s_[ns][0] + s_[ns][1];
            ls1 += s_[ns][2] + s_[ns][3];
        }
        ls0 += __shfl_xor_sync(0xffffffffu, ls0, 1);
        ls0 += __shfl_xor_sync(0xffffffffu, ls0, 2);
        ls1 += __shfl_xor_sync(0xffffffffu, ls1, 1);
        ls1 += __shfl_xor_sync(0xffffffffu, ls1, 2);
        l0 = l0 * corr0 + ls0;
        l1 = l1 * corr1 + ls1;

        #pragma unroll
        for (int ns = 0; ns < 8; ns++) {
            o_[ns][0] *= corr0; o_[ns][1] *= corr0;
            o_[ns][2] *= corr1; o_[ns][3] *= corr1;
        }

        // ---- pack P -> bf16 A-fragments (layout identity) ----
        uint32_t pk[8][2];
        #pragma unroll
        for (int ns = 0; ns < 8; ns++) {
            pk[ns][0] = pack_bf16(s_[ns][0], s_[ns][1]);
            pk[ns][1] = pack_bf16(s_[ns][2], s_[ns][3]);
        }

        // ---- O += P @ V (bf16) ----
        #pragma unroll
        for (int ks = 0; ks < 4; ks++) {
            uint32_t a0 = pk[2*ks][0],   a1 = pk[2*ks][1];
            uint32_t a2 = pk[2*ks+1][0], a3 = pk[2*ks+1][1];
            #pragma unroll
            for (int ns = 0; ns < 8; ns++) {
                uint32_t b0 = *(const uint32_t*)&Vs[st][ns*8 + qr][ks*16 + 2*qc];
                uint32_t b1 = *(const uint32_t*)&Vs[st][ns*8 + qr][ks*16 + 2*qc + 8];
                mma_bf16(o_[ns], a0, a1, a2, a3, b0, b1);
            }
        }

        __syncthreads();                 // all warps done with stage st
        if (kt + 2 < 64) issue(kt + 2, st);
        CP_COMMIT();
    }

    // normalize + write [n,h,d,s]
    float inv0 = 1.0f / l0, inv1 = 1.0f / l1;
    #pragma unroll
    for (int ns = 0; ns < 8; ns++) {
        int d = ns * 8 + 2 * qc;
        g_A[(size_t)(g * HD + d)     * S_DIM + row0]     = o_[ns][0] * inv0;
        g_A[(size_t)(g * HD + d + 1) * S_DIM + row0]     = o_[ns][1] * inv0;
        g_A[(size_t)(g * HD + d)     * S_DIM + row0 + 8] = o_[ns][2] * inv1;
        g_A[(size_t)(g * HD + d + 1) * S_DIM + row0 + 8] = o_[ns][3] * inv1;
    }
}

// ---------------------------------------------------------------------------
// Output projection + residual: grid (S/64, C/128, 2), block 256.
// ---------------------------------------------------------------------------
__global__ __launch_bounds__(256) void oproj_kernel(
    const float* __restrict__ x, const float* __restrict__ Wo,
    const float* __restrict__ bo, const float* __restrict__ gamma,
    float* __restrict__ out)
{
    __shared__ GemmSmem sm;

    const int n  = blockIdx.z;
    const int o0 = blockIdx.y * 128, s0 = blockIdx.x * 64;
    const float* Bg = g_A + (size_t)n * C_DIM * S_DIM;

    const int t    = threadIdx.x;
    const int lane = t & 31;
    const int w    = t >> 5;
    const int qr   = lane >> 2;
    const int qc   = lane & 3;

    float acc[8][4];
    #pragma unroll
    for (int ns = 0; ns < 8; ns++)
        #pragma unroll
        for (int j = 0; j < 4; j++) acc[ns][j] = 0.f;

    gemm_tile_tc(sm, Wo, Bg, o0, s0, acc, t);

    const float gam = gamma[0];
    const int r0 = o0 + w * 16 + qr;
    const int r1 = r0 + 8;
    const float bi0 = bo[r0], bi1 = bo[r1];

    #pragma unroll
    for (int ns = 0; ns < 8; ns++) {
        int col = s0 + ns * 8 + 2 * qc;
        size_t i0 = (size_t)(n * C_DIM + r0) * S_DIM + col;
        size_t i1 = (size_t)(n * C_DIM + r1) * S_DIM + col;
        float2 x0 = *(const float2*)&x[i0];
        float2 x1 = *(const float2*)&x[i1];
        float2 v0 = { gam * (acc[ns][0] + bi0) + x0.x,
                      gam * (acc[ns][1] + bi0) + x0.y };
        float2 v1 = { gam * (acc[ns][2] + bi1) + x1.x,
                      gam * (acc[ns][3] + bi1) + x1.y };
        *(float2*)&out[i0] = v0;
        *(float2*)&out[i1] = v1;
    }
}

// ---------------------------------------------------------------------------
extern "C" void kernel_launch(void* const* d_in, const int* in_sizes, int n_in,
                              void* d_out, int out_size)
{
    const float* x     = (const float*)d_in[0];
    const float* Wq    = (const float*)d_in[1];
    const float* bq    = (const float*)d_in[2];
    const float* Wk    = (const float*)d_in[3];
    const float* bk    = (const float*)d_in[4];
    const float* Wv    = (const float*)d_in[5];
    const float* bv    = (const float*)d_in[6];
    const float* Wo    = (const float*)d_in[7];
    const float* bo    = (const float*)d_in[8];
    const float* gamma = (const float*)d_in[9];
    float* out = (float*)d_out;

    dim3 gproj(S_DIM / 64, C_DIM / 128, 2 * 3);
    proj_kernel<<<gproj, 256>>>(x, Wq, bq, Wk, bk, Wv, bv);

    dim3 gattn(S_DIM / 128, 16);
    attn_kernel<<<gattn, 256>>>();

    dim3 gout(S_DIM / 64, C_DIM / 128, 2);
    oproj_kernel<<<gout, 256>>>(x, Wo, bo, gamma, out);
}

// round 7
// speedup vs baseline: 6.7519x; 1.1546x over previous
#include <cuda_runtime.h>
#include <cuda_bf16.h>
#include <cstdint>

#define C_DIM 512
#define S_DIM 4096
#define NH 8
#define HD 64

// Scratch (allocation-free rule: static __device__ globals)
__device__ __nv_bfloat16 g_xb[2 * S_DIM * C_DIM];    // x, token-major [n,s,c] bf16
__device__ __nv_bfloat16 g_Wb[4 * C_DIM * C_DIM];    // Wq,Wk,Wv,Wo bf16 [o][k]
__device__ __nv_bfloat16 g_Qb[2 * NH * S_DIM * HD];  // [n,h,s,d] bf16, 0.125*log2e folded
__device__ __nv_bfloat16 g_Kb[2 * NH * S_DIM * HD];  // [n,h,s,d] bf16
__device__ __nv_bfloat16 g_V [2 * C_DIM * S_DIM];    // [n,h,d,s] bf16
__device__ __nv_bfloat16 g_Ab[2 * S_DIM * C_DIM];    // attn out, token-major [n,s,c] bf16

// ---------------------------------------------------------------------------
// helpers
// ---------------------------------------------------------------------------
__device__ __forceinline__ float ex2f(float x) {
    float y;
    asm("ex2.approx.ftz.f32 %0, %1;" : "=f"(y) : "f"(x));
    return y;
}

__device__ __forceinline__ uint32_t pack_bf16(float lo, float hi) {
    uint32_t r;
    asm("cvt.rn.bf16x2.f32 %0, %1, %2;" : "=r"(r) : "f"(hi), "f"(lo));
    return r;
}

__device__ __forceinline__ void mma_bf16(float* d, uint32_t a0, uint32_t a1,
                                         uint32_t a2, uint32_t a3,
                                         uint32_t b0, uint32_t b1) {
    asm volatile(
        "mma.sync.aligned.m16n8k16.row.col.f32.bf16.bf16.f32 "
        "{%0,%1,%2,%3}, {%4,%5,%6,%7}, {%8,%9}, {%0,%1,%2,%3};"
        : "+f"(d[0]), "+f"(d[1]), "+f"(d[2]), "+f"(d[3])
        : "r"(a0), "r"(a1), "r"(a2), "r"(a3), "r"(b0), "r"(b1));
}

__device__ __forceinline__ void cp16(void* smem, const void* gmem) {
    uint32_t s = (uint32_t)__cvta_generic_to_shared(smem);
    asm volatile("cp.async.cg.shared.global [%0], [%1], 16;" :: "r"(s), "l"(gmem));
}
#define CP_COMMIT() asm volatile("cp.async.commit_group;")
#define CP_WAIT1()  asm volatile("cp.async.wait_group 1;")

// ---------------------------------------------------------------------------
// Prepass 1: x [n,c,s] f32 -> g_xb [n,s,c] bf16 (smem tile transpose)
// grid (S/32, C/32, 2), block (32,8)
// ---------------------------------------------------------------------------
__global__ void conv_x_kernel(const float* __restrict__ x)
{
    __shared__ float tile[32][33];
    const int s0 = blockIdx.x * 32, c0 = blockIdx.y * 32, n = blockIdx.z;
    const int tx = threadIdx.x, ty = threadIdx.y;

    #pragma unroll
    for (int i = ty; i < 32; i += 8)
        tile[i][tx] = x[((size_t)(n * C_DIM + c0 + i)) * S_DIM + s0 + tx];
    __syncthreads();
    #pragma unroll
    for (int i = ty; i < 32; i += 8)
        g_xb[((size_t)(n * S_DIM + s0 + i)) * C_DIM + c0 + tx] =
            __float2bfloat16(tile[tx][i]);
}

// ---------------------------------------------------------------------------
// Prepass 2: weights f32 -> bf16 (layout preserved [o][k])
// grid (256, 4), block 256; each thread converts one float4.
// ---------------------------------------------------------------------------
__global__ void conv_w_kernel(const float* __restrict__ Wq, const float* __restrict__ Wk,
                              const float* __restrict__ Wv, const float* __restrict__ Wo)
{
    const float* src[4] = {Wq, Wk, Wv, Wo};
    const int which = blockIdx.y;
    const int idx = blockIdx.x * 256 + threadIdx.x;   // float4 index
    float4 v = *(const float4*)&src[which][idx * 4];
    uint2 p;
    p.x = pack_bf16(v.x, v.y);
    p.y = pack_bf16(v.z, v.w);
    *(uint2*)&g_Wb[(size_t)which * C_DIM * C_DIM + idx * 4] = p;
}

// ---------------------------------------------------------------------------
// bf16 GEMM tile body, cp.async double-buffered.
// Block 256 thr (8 warps). Tile M=128 (rows of A/out), N=64 (tokens), K chunk 32.
// A: weights bf16 [M,K] k-contig. B: activations bf16 [token][k] k-contig (stride C_DIM).
// acc[ns][0..3]: rows {w*16+qr, +8} x cols {s0+ns*8+2qc, +1}.
// ---------------------------------------------------------------------------
struct GemmSmemB {
    __nv_bfloat16 Ws[2][128][40];   // pad 40 -> conflict-free u32 frag loads
    __nv_bfloat16 Bs[2][64][40];
};

__device__ __forceinline__ void gemm_bf16_pipe(
    GemmSmemB& sm, const __nv_bfloat16* __restrict__ A_gm,
    const __nv_bfloat16* __restrict__ B_gm,
    int o0, int s0, float acc[8][4], int t)
{
    const int lane = t & 31;
    const int w    = t >> 5;
    const int qr   = lane >> 2;
    const int qc   = lane & 3;
    const int row0 = w * 16 + qr;

    auto issue = [&](int ch, int st) {
        const int k0 = ch * 32;
        #pragma unroll
        for (int it = 0; it < 2; it++) {
            int e = t + 256 * it;
            int r = e >> 2, c8 = (e & 3) * 8;
            cp16(&sm.Ws[st][r][c8], A_gm + (size_t)(o0 + r) * C_DIM + k0 + c8);
        }
        {
            int r = t >> 2, c8 = (t & 3) * 8;
            cp16(&sm.Bs[st][r][c8], B_gm + (size_t)(s0 + r) * C_DIM + k0 + c8);
        }
    };

    issue(0, 0); CP_COMMIT();
    issue(1, 1); CP_COMMIT();

    for (int ch = 0; ch < 16; ch++) {
        const int st = ch & 1;
        CP_WAIT1();
        __syncthreads();

        #pragma unroll
        for (int ks = 0; ks < 2; ks++) {
            int c = ks * 16 + 2 * qc;
            uint32_t a0 = *(const uint32_t*)&sm.Ws[st][row0    ][c];
            uint32_t a1 = *(const uint32_t*)&sm.Ws[st][row0 + 8][c];
            uint32_t a2 = *(const uint32_t*)&sm.Ws[st][row0    ][c + 8];
            uint32_t a3 = *(const uint32_t*)&sm.Ws[st][row0 + 8][c + 8];
            #pragma unroll
            for (int ns = 0; ns < 8; ns++) {
                uint32_t b0 = *(const uint32_t*)&sm.Bs[st][ns*8 + qr][c];
                uint32_t b1 = *(const uint32_t*)&sm.Bs[st][ns*8 + qr][c + 8];
                mma_bf16(acc[ns], a0, a1, a2, a3, b0, b1);
            }
        }

        __syncthreads();
        if (ch + 2 < 16) issue(ch + 2, st);
        CP_COMMIT();
    }
}

// ---------------------------------------------------------------------------
// QKV projection: grid (S/64, C/128, 6), block 256.
// ---------------------------------------------------------------------------
__global__ __launch_bounds__(256) void proj_kernel(
    const float* __restrict__ bq, const float* __restrict__ bk,
    const float* __restrict__ bv)
{
    __shared__ GemmSmemB sm;

    const int z = blockIdx.z;
    const int n = z / 3, which = z % 3;
    const __nv_bfloat16* W = g_Wb + (size_t)which * C_DIM * C_DIM;
    const float* bias = (which == 0) ? bq : (which == 1) ? bk : bv;

    const int o0 = blockIdx.y * 128;
    const int s0 = blockIdx.x * 64;
    const __nv_bfloat16* xb = g_xb + (size_t)n * S_DIM * C_DIM;

    const int t    = threadIdx.x;
    const int lane = t & 31;
    const int w    = t >> 5;
    const int qr   = lane >> 2;
    const int qc   = lane & 3;

    float acc[8][4];
    #pragma unroll
    for (int ns = 0; ns < 8; ns++)
        #pragma unroll
        for (int j = 0; j < 4; j++) acc[ns][j] = 0.f;

    gemm_bf16_pipe(sm, W, xb, o0, s0, acc, t);

    const int r0 = o0 + w * 16 + qr;
    const int r1 = r0 + 8;
    const float bi0 = bias[r0], bi1 = bias[r1];

    if (which == 2) {
        // V -> bf16, d-major [n,h,d,s]
        #pragma unroll
        for (int ns = 0; ns < 8; ns++) {
            int col = s0 + ns * 8 + 2 * qc;
            *(uint32_t*)&g_V[(size_t)(n * C_DIM + r0) * S_DIM + col] =
                pack_bf16(acc[ns][0] + bi0, acc[ns][1] + bi0);
            *(uint32_t*)&g_V[(size_t)(n * C_DIM + r1) * S_DIM + col] =
                pack_bf16(acc[ns][2] + bi1, acc[ns][3] + bi1);
        }
    } else {
        __nv_bfloat16* outb = (which == 0) ? g_Qb : g_Kb;
        const float mult = (which == 0) ? 0.125f * 1.4426950408889634f : 1.0f;
        const int h0 = r0 >> 6, d0 = r0 & 63;
        const int h1 = r1 >> 6, d1 = r1 & 63;
        #pragma unroll
        for (int ns = 0; ns < 8; ns++) {
            int col = s0 + ns * 8 + 2 * qc;
            size_t b0i = ((size_t)(n * NH + h0) * S_DIM + col) * HD + d0;
            size_t b1i = ((size_t)(n * NH + h1) * S_DIM + col) * HD + d1;
            outb[b0i]      = __float2bfloat16((acc[ns][0] + bi0) * mult);
            outb[b0i + HD] = __float2bfloat16((acc[ns][1] + bi0) * mult);
            outb[b1i]      = __float2bfloat16((acc[ns][2] + bi1) * mult);
            outb[b1i + HD] = __float2bfloat16((acc[ns][3] + bi1) * mult);
        }
    }
}

// ---------------------------------------------------------------------------
// Flash attention: all-bf16 MMA, cp.async double-buffered K/V (verified R5).
// Output now bf16 token-major [n,s,c]. Block 256, grid (S/128, 16).
// ---------------------------------------------------------------------------
__global__ __launch_bounds__(256) void attn_kernel()
{
    __shared__ __nv_bfloat16 Ks[2][64][72];   // [stage][key][d]
    __shared__ __nv_bfloat16 Vs[2][64][72];   // [stage][d][key]

    const int g  = blockIdx.y;                // n*8 + h
    const int q0 = blockIdx.x * 128;
    const __nv_bfloat16* Qg = g_Qb + (size_t)g * S_DIM * HD;
    const __nv_bfloat16* Kg = g_Kb + (size_t)g * S_DIM * HD;
    const __nv_bfloat16* Vg = g_V  + (size_t)g * HD * S_DIM;

    const int t    = threadIdx.x;
    const int w    = t >> 5;
    const int lane = t & 31;
    const int qr   = lane >> 2;
    const int qc   = lane & 3;
    const int row0 = q0 + w * 16 + qr;

    auto issue = [&](int kt, int st) {
        const int k0 = kt * 64;
        #pragma unroll
        for (int it = 0; it < 2; it++) {
            int e = t + 256 * it;
            int r = e >> 3, c8 = (e & 7) * 8;
            cp16(&Ks[st][r][c8], Kg + (size_t)(k0 + r) * HD + c8);
        }
        #pragma unroll
        for (int it = 0; it < 2; it++) {
            int e = t + 256 * it;
            int r = e >> 3, c8 = (e & 7) * 8;
            cp16(&Vs[st][r][c8], Vg + (size_t)r * S_DIM + k0 + c8);
        }
    };

    issue(0, 0); CP_COMMIT();
    issue(1, 1); CP_COMMIT();

    uint32_t qa[4][4];
    #pragma unroll
    for (int ks = 0; ks < 4; ks++) {
        int c = ks * 16 + 2 * qc;
        qa[ks][0] = *(const uint32_t*)&Qg[(size_t)row0       * HD + c];
        qa[ks][1] = *(const uint32_t*)&Qg[(size_t)(row0 + 8) * HD + c];
        qa[ks][2] = *(const uint32_t*)&Qg[(size_t)row0       * HD + c + 8];
        qa[ks][3] = *(const uint32_t*)&Qg[(size_t)(row0 + 8) * HD + c + 8];
    }

    float o_[8][4];
    #pragma unroll
    for (int ns = 0; ns < 8; ns++)
        #pragma unroll
        for (int j = 0; j < 4; j++) o_[ns][j] = 0.f;
    float m0 = -1e30f, m1 = -1e30f, l0 = 0.f, l1 = 0.f;

    for (int kt = 0; kt < 64; kt++) {
        const int st = kt & 1;
        CP_WAIT1();
        __syncthreads();

        float s_[8][4];
        #pragma unroll
        for (int ns = 0; ns < 8; ns++)
            #pragma unroll
            for (int j = 0; j < 4; j++) s_[ns][j] = 0.f;

        #pragma unroll
        for (int ks = 0; ks < 4; ks++) {
            #pragma unroll
            for (int ns = 0; ns < 8; ns++) {
                uint32_t b0 = *(const uint32_t*)&Ks[st][ns*8 + qr][ks*16 + 2*qc];
                uint32_t b1 = *(const uint32_t*)&Ks[st][ns*8 + qr][ks*16 + 2*qc + 8];
                mma_bf16(s_[ns], qa[ks][0], qa[ks][1], qa[ks][2], qa[ks][3], b0, b1);
            }
        }

        float mt0 = -1e30f, mt1 = -1e30f;
        #pragma unroll
        for (int ns = 0; ns < 8; ns++) {
            mt0 = fmaxf(mt0, fmaxf(s_[ns][0], s_[ns][1]));
            mt1 = fmaxf(mt1, fmaxf(s_[ns][2], s_[ns][3]));
        }
        mt0 = fmaxf(mt0, __shfl_xor_sync(0xffffffffu, mt0, 1));
        mt0 = fmaxf(mt0, __shfl_xor_sync(0xffffffffu, mt0, 2));
        mt1 = fmaxf(mt1, __shfl_xor_sync(0xffffffffu, mt1, 1));
        mt1 = fmaxf(mt1, __shfl_xor_sync(0xffffffffu, mt1, 2));

        float mn0 = fmaxf(m0, mt0), mn1 = fmaxf(m1, mt1);
        float corr0 = ex2f(m0 - mn0), corr1 = ex2f(m1 - mn1);
        m0 = mn0; m1 = mn1;

        float ls0 = 0.f, ls1 = 0.f;
        #pragma unroll
        for (int ns = 0; ns < 8; ns++) {
            s_[ns][0] = ex2f(s_[ns][0] - mn0);
            s_[ns][1] = ex2f(s_[ns][1] - mn0);
            s_[ns][2] = ex2f(s_[ns][2] - mn1);
            s_[ns][3] = ex2f(s_[ns][3] - mn1);
            ls0 += s_[ns][0] + s_[ns][1];
            ls1 += s_[ns][2] + s_[ns][3];
        }
        ls0 += __shfl_xor_sync(0xffffffffu, ls0, 1);
        ls0 += __shfl_xor_sync(0xffffffffu, ls0, 2);
        ls1 += __shfl_xor_sync(0xffffffffu, ls1, 1);
        ls1 += __shfl_xor_sync(0xffffffffu, ls1, 2);
        l0 = l0 * corr0 + ls0;
        l1 = l1 * corr1 + ls1;

        #pragma unroll
        for (int ns = 0; ns < 8; ns++) {
            o_[ns][0] *= corr0; o_[ns][1] *= corr0;
            o_[ns][2] *= corr1; o_[ns][3] *= corr1;
        }

        uint32_t pk[8][2];
        #pragma unroll
        for (int ns = 0; ns < 8; ns++) {
            pk[ns][0] = pack_bf16(s_[ns][0], s_[ns][1]);
            pk[ns][1] = pack_bf16(s_[ns][2], s_[ns][3]);
        }

        #pragma unroll
        for (int ks = 0; ks < 4; ks++) {
            uint32_t a0 = pk[2*ks][0],   a1 = pk[2*ks][1];
            uint32_t a2 = pk[2*ks+1][0], a3 = pk[2*ks+1][1];
            #pragma unroll
            for (int ns = 0; ns < 8; ns++) {
                uint32_t b0 = *(const uint32_t*)&Vs[st][ns*8 + qr][ks*16 + 2*qc];
                uint32_t b1 = *(const uint32_t*)&Vs[st][ns*8 + qr][ks*16 + 2*qc + 8];
                mma_bf16(o_[ns], a0, a1, a2, a3, b0, b1);
            }
        }

        __syncthreads();
        if (kt + 2 < 64) issue(kt + 2, st);
        CP_COMMIT();
    }

    // normalize + write bf16 token-major [n,s,c], c = h*64 + d
    const int n = g >> 3, h = g & 7;
    float inv0 = 1.0f / l0, inv1 = 1.0f / l1;
    #pragma unroll
    for (int ns = 0; ns < 8; ns++) {
        int d = ns * 8 + 2 * qc;
        size_t base = ((size_t)(n * S_DIM + row0)) * C_DIM + h * HD + d;
        *(uint32_t*)&g_Ab[base] = pack_bf16(o_[ns][0] * inv0, o_[ns][1] * inv0);
        *(uint32_t*)&g_Ab[base + (size_t)8 * C_DIM] =
            pack_bf16(o_[ns][2] * inv1, o_[ns][3] * inv1);
    }
}

// ---------------------------------------------------------------------------
// Output projection + residual: grid (S/64, C/128, 2), block 256.
// ---------------------------------------------------------------------------
__global__ __launch_bounds__(256) void oproj_kernel(
    const float* __restrict__ x, const float* __restrict__ bo,
    const float* __restrict__ gamma, float* __restrict__ out)
{
    __shared__ GemmSmemB sm;

    const int n  = blockIdx.z;
    const int o0 = blockIdx.y * 128, s0 = blockIdx.x * 64;
    const __nv_bfloat16* Wo = g_Wb + (size_t)3 * C_DIM * C_DIM;
    const __nv_bfloat16* Bg = g_Ab + (size_t)n * S_DIM * C_DIM;

    const int t    = threadIdx.x;
    const int lane = t & 31;
    const int w    = t >> 5;
    const int qr   = lane >> 2;
    const int qc   = lane & 3;

    float acc[8][4];
    #pragma unroll
    for (int ns = 0; ns < 8; ns++)
        #pragma unroll
        for (int j = 0; j < 4; j++) acc[ns][j] = 0.f;

    gemm_bf16_pipe(sm, Wo, Bg, o0, s0, acc, t);

    const float gam = gamma[0];
    const int r0 = o0 + w * 16 + qr;
    const int r1 = r0 + 8;
    const float bi0 = bo[r0], bi1 = bo[r1];

    #pragma unroll
    for (int ns = 0; ns < 8; ns++) {
        int col = s0 + ns * 8 + 2 * qc;
        size_t i0 = (size_t)(n * C_DIM + r0) * S_DIM + col;
        size_t i1 = (size_t)(n * C_DIM + r1) * S_DIM + col;
        float2 x0 = *(const float2*)&x[i0];
        float2 x1 = *(const float2*)&x[i1];
        float2 v0 = { gam * (acc[ns][0] + bi0) + x0.x,
                      gam * (acc[ns][1] + bi0) + x0.y };
        float2 v1 = { gam * (acc[ns][2] + bi1) + x1.x,
                      gam * (acc[ns][3] + bi1) + x1.y };
        *(float2*)&out[i0] = v0;
        *(float2*)&out[i1] = v1;
    }
}

// ---------------------------------------------------------------------------
extern "C" void kernel_launch(void* const* d_in, const int* in_sizes, int n_in,
                              void* d_out, int out_size)
{
    const float* x     = (const float*)d_in[0];
    const float* Wq    = (const float*)d_in[1];
    const float* bq    = (const float*)d_in[2];
    const float* Wk    = (const float*)d_in[3];
    const float* bk    = (const float*)d_in[4];
    const float* Wv    = (const float*)d_in[5];
    const float* bv    = (const float*)d_in[6];
    const float* Wo    = (const float*)d_in[7];
    const float* bo    = (const float*)d_in[8];
    const float* gamma = (const float*)d_in[9];
    float* out = (float*)d_out;

    dim3 gcx(S_DIM / 32, C_DIM / 32, 2);
    conv_x_kernel<<<gcx, dim3(32, 8)>>>(x);
    conv_w_kernel<<<dim3(256, 4), 256>>>(Wq, Wk, Wv, Wo);

    dim3 gproj(S_DIM / 64, C_DIM / 128, 2 * 3);
    proj_kernel<<<gproj, 256>>>(bq, bk, bv);

    dim3 gattn(S_DIM / 128, 16);
    attn_kernel<<<gattn, 256>>>();

    dim3 gout(S_DIM / 64, C_DIM / 128, 2);
    oproj_kernel<<<gout, 256>>>(x, bo, gamma, out);
}